// round 13
// baseline (speedup 1.0000x reference)
#include <cuda_runtime.h>
#include <cuda_fp16.h>
#include <mma.h>

using namespace nvcuda;

#define HID 128
#define NMAX 100000
#define NPAD 100096
#define EMAX 1600000
#define GMAX 64
#define SCAN_B 512
#define LDAB 136            // fp16 row stride in smem (padded)
#define LDC  132            // fp32 staging row stride

// ---- scratch (static device globals; no allocation) ----
__device__ uint2 g_m[(size_t)NPAD * 32];   // fp16 messages m=(dis*A)@W, [node][128]
__device__ uint2 g_y[(size_t)NPAD * 32];   // fp16 activations relu(agg+bias)
__device__ __align__(16) __half g_wh[3 * HID * HID];  // fp16 weights
__device__ float g_dis[NMAX];              // deg^{-1/2}
__device__ float g_cnt[GMAX];
__device__ int   g_deg[NMAX];
__device__ int   g_cur[NMAX];
__device__ int   g_rowptr[NMAX + 1];
__device__ __align__(16) int g_csr[EMAX];
__device__ int   g_blksum[(NMAX + SCAN_B - 1) / SCAN_B];

__device__ __forceinline__ int clampi(int v, int hi) {
    return v < 0 ? 0 : (v > hi ? hi : v);
}

// ---- fp16 pack/unpack ----
__device__ __forceinline__ unsigned pack_hf2(float lo, float hi) {
    __half2 h = __floats2half2_rn(lo, hi);
    return *(unsigned*)&h;
}
__device__ __forceinline__ float4 unpk_hf4(uint2 v) {
    float2 f0 = __half22float2(*(__half2*)&v.x);
    float2 f1 = __half22float2(*(__half2*)&v.y);
    return make_float4(f0.x, f0.y, f1.x, f1.y);
}

// ---------------------------------------------------------------------------
// init: zero deg/cur/cnt/out + convert all 3 W matrices to fp16
// ---------------------------------------------------------------------------
__global__ void k_init(const float* __restrict__ Ws,
                       float* __restrict__ out, int N, int out_elems) {
    int i = blockIdx.x * blockDim.x + threadIdx.x;
    if (i < N) { g_deg[i] = 0; g_cur[i] = 0; }
    if (i < GMAX) g_cnt[i] = 0.0f;
    if (i < out_elems) out[i] = 0.0f;
    if (i < 3 * HID * HID / 4) {
        float4 v = ((const float4*)Ws)[i];
        ((uint2*)g_wh)[i] = make_uint2(pack_hf2(v.x, v.y), pack_hf2(v.z, v.w));
    }
}

__global__ void k_count(const int* __restrict__ dst, int E, int N) {
    int e = blockIdx.x * blockDim.x + threadIdx.x;
    if (e < E) atomicAdd(&g_deg[clampi(dst[e], N - 1)], 1);
}

// scan stage 1 + dis = rsqrt(deg+1)
__global__ void k_scan1(int N) {
    __shared__ int sm[SCAN_B];
    int t = threadIdx.x;
    int i = blockIdx.x * SCAN_B + t;
    int v = (i < N) ? g_deg[i] : 0;
    sm[t] = v;
    __syncthreads();
    #pragma unroll
    for (int off = 1; off < SCAN_B; off <<= 1) {
        int x = (t >= off) ? sm[t - off] : 0;
        __syncthreads();
        sm[t] += x;
        __syncthreads();
    }
    if (i < N) {
        g_rowptr[i] = sm[t] - v;
        g_dis[i] = rsqrtf((float)(v + 1));
    }
    if (t == SCAN_B - 1) g_blksum[blockIdx.x] = sm[t];
}

__global__ void k_scan2(int nb) {
    __shared__ int sm[SCAN_B];
    int t = threadIdx.x;
    int v = (t < nb) ? g_blksum[t] : 0;
    sm[t] = v;
    __syncthreads();
    #pragma unroll
    for (int off = 1; off < SCAN_B; off <<= 1) {
        int x = (t >= off) ? sm[t - off] : 0;
        __syncthreads();
        sm[t] += x;
        __syncthreads();
    }
    if (t < nb) g_blksum[t] = sm[t] - v;
}

__global__ void k_scan3(int N, int E) {
    int i = blockIdx.x * blockDim.x + threadIdx.x;
    if (i < N) g_rowptr[i] += g_blksum[i / SCAN_B];
    if (i == 0) g_rowptr[N] = E;
}

__global__ void k_fill(const int* __restrict__ src,
                       const int* __restrict__ dst, int E, int N) {
    int e = blockIdx.x * blockDim.x + threadIdx.x;
    if (e >= E) return;
    int d = clampi(dst[e], N - 1);
    int pos = atomicAdd(&g_cur[d], 1);
    int idx = clampi(g_rowptr[d] + pos, EMAX - 1);
    g_csr[idx] = clampi(src[e], N - 1);
}

// ---------------------------------------------------------------------------
// WMMA GEMM tile: m[r] = fp16( (dis[r]*A[r]) @ W ),  A = x (l0) or g_y.
// 256 threads = 8 warps; warp w: rows (w&3)*32..+31, cols (w>>2)*64..+63.
// Per k-step: 2 A-frag + 4 B-frag loads -> 8 MMAs (was 9 loads / 8 MMAs).
// ---------------------------------------------------------------------------
__global__ void __launch_bounds__(256) k_gemm_wmma(
    const float* __restrict__ xin,
    int layer, int N)
{
    extern __shared__ char smch[];
    __half* As = (__half*)smch;               // [128][LDAB]
    __half* Bs = As + 128 * LDAB;             // [128][LDAB]
    float*  Cs = (float*)smch;                // [128][LDC] (reuse)

    const int tid  = threadIdx.x;
    const int w    = tid >> 5;
    const int base = blockIdx.x * 128;
    const __half* Wh = g_wh + (size_t)layer * HID * HID;

    // --- W(fp16) -> Bs, k-major rows: 2048 uint4, 8 per thread ---
    {
        const uint4* Wv = (const uint4*)Wh;
        #pragma unroll
        for (int i = 0; i < 8; i++) {
            int o = i * 256 + tid;          // uint4 index; 16 per row
            int k = o >> 4, q = o & 15;
            *(uint4*)(Bs + k * LDAB + q * 8) = Wv[o];
        }
    }
    // --- A -> As (fp16), scaled by dis[row] ---
    {
        #pragma unroll
        for (int i = 0; i < 16; i++) {
            int o = i * 256 + tid;
            int r = o >> 5, q = o & 31;     // float4/uint2 granularity
            uint2 u = make_uint2(0u, 0u);
            if (base + r < N) {
                float ds = g_dis[clampi(base + r, NMAX - 1)];
                if (layer == 0) {
                    float4 v = ((const float4*)(xin + (size_t)(base + r) * HID))[q];
                    u = make_uint2(pack_hf2(v.x * ds, v.y * ds),
                                   pack_hf2(v.z * ds, v.w * ds));
                } else {
                    u = g_y[(size_t)(base + r) * 32 + q];
                    __half2 d2 = __float2half2_rn(ds);
                    *(__half2*)&u.x = __hmul2(*(__half2*)&u.x, d2);
                    *(__half2*)&u.y = __hmul2(*(__half2*)&u.y, d2);
                }
            }
            *(uint2*)(As + r * LDAB + q * 4) = u;
        }
    }
    __syncthreads();

    // --- compute: warp = 32 rows x 64 cols = 2x4 accumulators ---
    const int wr = (w & 3) * 32;
    const int wc = (w >> 2) * 64;

    wmma::fragment<wmma::accumulator, 16, 16, 16, float> acc[2][4];
    #pragma unroll
    for (int i = 0; i < 2; i++)
        #pragma unroll
        for (int j = 0; j < 4; j++) wmma::fill_fragment(acc[i][j], 0.0f);

    #pragma unroll
    for (int ks = 0; ks < 8; ks++) {
        wmma::fragment<wmma::matrix_a, 16, 16, 16, __half, wmma::row_major> af[2];
        wmma::load_matrix_sync(af[0], As + (wr +  0) * LDAB + ks * 16, LDAB);
        wmma::load_matrix_sync(af[1], As + (wr + 16) * LDAB + ks * 16, LDAB);
        #pragma unroll
        for (int j = 0; j < 4; j++) {
            wmma::fragment<wmma::matrix_b, 16, 16, 16, __half, wmma::row_major> bf;
            wmma::load_matrix_sync(bf, Bs + (ks * 16) * LDAB + wc + j * 16, LDAB);
            wmma::mma_sync(acc[0][j], af[0], bf, acc[0][j]);
            wmma::mma_sync(acc[1][j], af[1], bf, acc[1][j]);
        }
    }
    __syncthreads();            // done reading As/Bs; reuse as staging

    #pragma unroll
    for (int i = 0; i < 2; i++)
        #pragma unroll
        for (int j = 0; j < 4; j++)
            wmma::store_matrix_sync(Cs + (wr + i * 16) * LDC + wc + j * 16,
                                    acc[i][j], LDC, wmma::mem_row_major);
    __syncthreads();

    // --- epilogue: pack fp16 (dis already folded), store g_m coalesced ---
    {
        int r    = tid >> 1;
        int half = tid & 1;
        int m    = base + r;
        if (m < N) {
            const float* row = Cs + r * LDC + half * 64;
            uint4* dst = (uint4*)g_m + (size_t)m * 16 + half * 8;
            #pragma unroll
            for (int i = 0; i < 4; i++) {
                float4 p = *(const float4*)(row + i * 16 + 0);
                float4 q = *(const float4*)(row + i * 16 + 4);
                float4 s = *(const float4*)(row + i * 16 + 8);
                float4 t = *(const float4*)(row + i * 16 + 12);
                uint4 u0, u1;
                u0.x = pack_hf2(p.x, p.y); u0.y = pack_hf2(p.z, p.w);
                u0.z = pack_hf2(q.x, q.y); u0.w = pack_hf2(q.z, q.w);
                u1.x = pack_hf2(s.x, s.y); u1.y = pack_hf2(s.z, s.w);
                u1.z = pack_hf2(t.x, t.y); u1.w = pack_hf2(t.z, t.w);
                dst[i * 2 + 0] = u0;
                dst[i * 2 + 1] = u1;
            }
        }
    }
}

// ---------------------------------------------------------------------------
// aggregate: warp per node. y[n] = relu( dn*(sum_in m[s] + m[n]) + bias )
// unroll x8, 4 accumulators for MLP.
// ---------------------------------------------------------------------------
__device__ __forceinline__ void add_row(float4& a, int s, int lane) {
    float4 g = unpk_hf4(g_m[(size_t)s * 32 + lane]);
    a.x += g.x; a.y += g.y; a.z += g.z; a.w += g.w;
}

__global__ void __launch_bounds__(256) k_aggr(const float* __restrict__ bias, int N) {
    int w    = (int)((blockIdx.x * (unsigned)blockDim.x + threadIdx.x) >> 5);
    int lane = threadIdx.x & 31;
    if (w >= N) return;

    int beg = clampi(g_rowptr[w],     EMAX);
    int end = clampi(g_rowptr[w + 1], EMAX);
    float dn = g_dis[w];

    float4 a0 = unpk_hf4(g_m[(size_t)w * 32 + lane]);   // self term m[n]
    float4 a1 = make_float4(0.f, 0.f, 0.f, 0.f);
    float4 a2 = make_float4(0.f, 0.f, 0.f, 0.f);
    float4 a3 = make_float4(0.f, 0.f, 0.f, 0.f);

    int e = beg;
    for (; e < end && (e & 3); e++) add_row(a0, g_csr[e], lane);
    for (; e + 8 <= end; e += 8) {
        int4 s4 = *(const int4*)(g_csr + e);
        int4 t4 = *(const int4*)(g_csr + e + 4);
        add_row(a0, s4.x, lane); add_row(a1, s4.y, lane);
        add_row(a2, s4.z, lane); add_row(a3, s4.w, lane);
        add_row(a0, t4.x, lane); add_row(a1, t4.y, lane);
        add_row(a2, t4.z, lane); add_row(a3, t4.w, lane);
    }
    for (; e + 4 <= end; e += 4) {
        int4 s4 = *(const int4*)(g_csr + e);
        add_row(a0, s4.x, lane); add_row(a1, s4.y, lane);
        add_row(a2, s4.z, lane); add_row(a3, s4.w, lane);
    }
    for (; e < end; e++) add_row(a3, g_csr[e], lane);

    float4 b = ((const float4*)bias)[lane];
    float y0 = fmaxf(dn * ((a0.x + a1.x) + (a2.x + a3.x)) + b.x, 0.0f);
    float y1 = fmaxf(dn * ((a0.y + a1.y) + (a2.y + a3.y)) + b.y, 0.0f);
    float y2 = fmaxf(dn * ((a0.z + a1.z) + (a2.z + a3.z)) + b.z, 0.0f);
    float y3 = fmaxf(dn * ((a0.w + a1.w) + (a2.w + a3.w)) + b.w, 0.0f);
    g_y[(size_t)w * 32 + lane] = make_uint2(pack_hf2(y0, y1), pack_hf2(y2, y3));
}

// ---------------------------------------------------------------------------
// pooling (batch sorted): y already has bias+relu
// ---------------------------------------------------------------------------
#define POOL_CHUNK 256
__global__ void __launch_bounds__(HID) k_pool(
    const int* __restrict__ batch,
    float* __restrict__ out,
    int N)
{
    int j     = threadIdx.x;
    int start = blockIdx.x * POOL_CHUNK;
    if (start >= N) return;
    int end = start + POOL_CHUNK;
    if (end > N) end = N;

    const __half* yh = (const __half*)g_y;

    int   cur = clampi(batch[start], GMAX - 1);
    float sum = 0.0f;
    float cnt = 0.0f;

    for (int r = start; r < end; r++) {
        int g = clampi(batch[r], GMAX - 1);
        if (g != cur) {
            atomicAdd(out + (size_t)cur * HID + j, sum);
            if (j == 0) atomicAdd(&g_cnt[cur], cnt);
            sum = 0.0f; cnt = 0.0f; cur = g;
        }
        sum += __half2float(yh[(size_t)r * HID + j]);
        cnt += 1.0f;
    }
    atomicAdd(out + (size_t)cur * HID + j, sum);
    if (j == 0) atomicAdd(&g_cnt[cur], cnt);
}

__global__ void k_div(float* __restrict__ out, int out_elems) {
    int i = blockIdx.x * blockDim.x + threadIdx.x;
    if (i < out_elems) out[i] /= fmaxf(g_cnt[i >> 7], 1.0f);
}

// ---------------------------------------------------------------------------
extern "C" void kernel_launch(void* const* d_in, const int* in_sizes, int n_in,
                              void* d_out, int out_size) {
    const float* x     = (const float*)d_in[0];
    const int*   ei    = (const int*)d_in[1];     // int32 (JAX x64 disabled)
    const int*   batch = (const int*)d_in[2];     // int32
    const float* Ws    = (const float*)d_in[3];
    const float* bs    = (const float*)d_in[4];
    float*       out   = (float*)d_out;

    const int N = in_sizes[0] / HID;
    const int E = in_sizes[1] / 2;
    const int* srcp = ei;
    const int* dstp = ei + E;

    const int smem = 2 * 128 * LDAB * sizeof(__half);   // 69632 B
    cudaFuncSetAttribute(k_gemm_wmma,
                         cudaFuncAttributeMaxDynamicSharedMemorySize, smem);

    const int nb_scan     = (N + SCAN_B - 1) / SCAN_B;
    const int gemm_blocks = (N + 127) / 128;
    const int aggr_blocks = (int)(((long long)N * 32 + 255) / 256);

    // launch order keeps layer-0 GEMM at index 3 (ncu capture slot)
    k_init  <<<(N + 255) / 256, 256>>>(Ws, out, N, out_size);           // 0
    k_count <<<(E + 255) / 256, 256>>>(dstp, E, N);                     // 1
    k_scan1 <<<nb_scan, SCAN_B>>>(N);                                   // 2
    k_gemm_wmma<<<gemm_blocks, 256, smem>>>(x, 0, N);                   // 3 <- profiled
    k_scan2 <<<1, SCAN_B>>>(nb_scan);                                   // 4
    k_scan3 <<<(N + 255) / 256, 256>>>(N, E);                           // 5
    k_fill  <<<(E + 255) / 256, 256>>>(srcp, dstp, E, N);               // 6

    k_aggr  <<<aggr_blocks, 256>>>(bs, N);                              // layer 0
    for (int l = 1; l < 3; l++) {
        k_gemm_wmma<<<gemm_blocks, 256, smem>>>(x, l, N);
        k_aggr  <<<aggr_blocks, 256>>>(bs + (size_t)l * HID, N);
    }

    k_pool<<<(N + POOL_CHUNK - 1) / POOL_CHUNK, HID>>>(batch, out, N);
    k_div <<<(out_size + 255) / 256, 256>>>(out, out_size);
}

// round 14
// speedup vs baseline: 1.1311x; 1.1311x over previous
#include <cuda_runtime.h>
#include <cuda_fp16.h>
#include <mma.h>

using namespace nvcuda;

#define HID 128
#define NMAX 100000
#define NPAD 100096
#define EMAX 1600000
#define GMAX 64
#define SCAN_B 512
#define LDAB 136            // fp16 row stride in smem (padded)
#define LDC  132            // fp32 staging row stride

// ---- scratch (static device globals; no allocation) ----
__device__ uint2 g_m[(size_t)NPAD * 32];   // fp16 messages m=(dis*A)@W, [node][128]
__device__ uint2 g_y[(size_t)NPAD * 32];   // fp16 activations relu(agg+bias)
__device__ __align__(16) __half g_wh[3 * HID * HID];  // fp16 weights
__device__ float g_dis[NMAX];              // deg^{-1/2}
__device__ float g_cnt[GMAX];
__device__ int   g_deg[NMAX];
__device__ int   g_cur[NMAX];
__device__ int   g_rowptr[NMAX + 1];
__device__ __align__(16) int g_csr[EMAX];
__device__ int   g_blksum[(NMAX + SCAN_B - 1) / SCAN_B];

__device__ __forceinline__ int clampi(int v, int hi) {
    return v < 0 ? 0 : (v > hi ? hi : v);
}

// ---- fp16 pack/unpack ----
__device__ __forceinline__ unsigned pack_hf2(float lo, float hi) {
    __half2 h = __floats2half2_rn(lo, hi);
    return *(unsigned*)&h;
}
__device__ __forceinline__ float4 unpk_hf4(uint2 v) {
    float2 f0 = __half22float2(*(__half2*)&v.x);
    float2 f1 = __half22float2(*(__half2*)&v.y);
    return make_float4(f0.x, f0.y, f1.x, f1.y);
}

// ---------------------------------------------------------------------------
// init: zero deg/cur/cnt/out + convert all 3 W matrices to fp16
// ---------------------------------------------------------------------------
__global__ void k_init(const float* __restrict__ Ws,
                       float* __restrict__ out, int N, int out_elems) {
    int i = blockIdx.x * blockDim.x + threadIdx.x;
    if (i < N) { g_deg[i] = 0; g_cur[i] = 0; }
    if (i < GMAX) g_cnt[i] = 0.0f;
    if (i < out_elems) out[i] = 0.0f;
    if (i < 3 * HID * HID / 4) {
        float4 v = ((const float4*)Ws)[i];
        ((uint2*)g_wh)[i] = make_uint2(pack_hf2(v.x, v.y), pack_hf2(v.z, v.w));
    }
}

__global__ void k_count(const int* __restrict__ dst, int E, int N) {
    int e = blockIdx.x * blockDim.x + threadIdx.x;
    if (e < E) atomicAdd(&g_deg[clampi(dst[e], N - 1)], 1);
}

// scan stage 1 + dis = rsqrt(deg+1)
__global__ void k_scan1(int N) {
    __shared__ int sm[SCAN_B];
    int t = threadIdx.x;
    int i = blockIdx.x * SCAN_B + t;
    int v = (i < N) ? g_deg[i] : 0;
    sm[t] = v;
    __syncthreads();
    #pragma unroll
    for (int off = 1; off < SCAN_B; off <<= 1) {
        int x = (t >= off) ? sm[t - off] : 0;
        __syncthreads();
        sm[t] += x;
        __syncthreads();
    }
    if (i < N) {
        g_rowptr[i] = sm[t] - v;
        g_dis[i] = rsqrtf((float)(v + 1));
    }
    if (t == SCAN_B - 1) g_blksum[blockIdx.x] = sm[t];
}

__global__ void k_scan2(int nb) {
    __shared__ int sm[SCAN_B];
    int t = threadIdx.x;
    int v = (t < nb) ? g_blksum[t] : 0;
    sm[t] = v;
    __syncthreads();
    #pragma unroll
    for (int off = 1; off < SCAN_B; off <<= 1) {
        int x = (t >= off) ? sm[t - off] : 0;
        __syncthreads();
        sm[t] += x;
        __syncthreads();
    }
    if (t < nb) g_blksum[t] = sm[t] - v;
}

__global__ void k_scan3(int N, int E) {
    int i = blockIdx.x * blockDim.x + threadIdx.x;
    if (i < N) g_rowptr[i] += g_blksum[i / SCAN_B];
    if (i == 0) g_rowptr[N] = E;
}

__global__ void k_fill(const int* __restrict__ src,
                       const int* __restrict__ dst, int E, int N) {
    int e = blockIdx.x * blockDim.x + threadIdx.x;
    if (e >= E) return;
    int d = clampi(dst[e], N - 1);
    int pos = atomicAdd(&g_cur[d], 1);
    int idx = clampi(g_rowptr[d] + pos, EMAX - 1);
    g_csr[idx] = clampi(src[e], N - 1);
}

// ---------------------------------------------------------------------------
// WMMA GEMM tile: m[r] = fp16( (dis[r]*A[r]) @ W ),  A = x (l0) or g_y.
// 256 threads = 8 warps; warp w: rows (w&3)*32..+31, cols (w>>2)*64..+63.
// ---------------------------------------------------------------------------
__global__ void __launch_bounds__(256) k_gemm_wmma(
    const float* __restrict__ xin,
    int layer, int N)
{
    extern __shared__ char smch[];
    __half* As = (__half*)smch;               // [128][LDAB]
    __half* Bs = As + 128 * LDAB;             // [128][LDAB]
    float*  Cs = (float*)smch;                // [128][LDC] (reuse)

    const int tid  = threadIdx.x;
    const int w    = tid >> 5;
    const int base = blockIdx.x * 128;
    const __half* Wh = g_wh + (size_t)layer * HID * HID;

    // --- W(fp16) -> Bs, k-major rows: 2048 uint4, 8 per thread ---
    {
        const uint4* Wv = (const uint4*)Wh;
        #pragma unroll
        for (int i = 0; i < 8; i++) {
            int o = i * 256 + tid;          // uint4 index; 16 per row
            int k = o >> 4, q = o & 15;
            *(uint4*)(Bs + k * LDAB + q * 8) = Wv[o];
        }
    }
    // --- A -> As (fp16), scaled by dis[row] ---
    {
        #pragma unroll
        for (int i = 0; i < 16; i++) {
            int o = i * 256 + tid;
            int r = o >> 5, q = o & 31;
            uint2 u = make_uint2(0u, 0u);
            if (base + r < N) {
                float ds = g_dis[clampi(base + r, NMAX - 1)];
                if (layer == 0) {
                    float4 v = ((const float4*)(xin + (size_t)(base + r) * HID))[q];
                    u = make_uint2(pack_hf2(v.x * ds, v.y * ds),
                                   pack_hf2(v.z * ds, v.w * ds));
                } else {
                    u = g_y[(size_t)(base + r) * 32 + q];
                    __half2 d2 = __float2half2_rn(ds);
                    *(__half2*)&u.x = __hmul2(*(__half2*)&u.x, d2);
                    *(__half2*)&u.y = __hmul2(*(__half2*)&u.y, d2);
                }
            }
            *(uint2*)(As + r * LDAB + q * 4) = u;
        }
    }
    __syncthreads();

    // --- compute: warp = 32 rows x 64 cols = 2x4 accumulators ---
    const int wr = (w & 3) * 32;
    const int wc = (w >> 2) * 64;

    wmma::fragment<wmma::accumulator, 16, 16, 16, float> acc[2][4];
    #pragma unroll
    for (int i = 0; i < 2; i++)
        #pragma unroll
        for (int j = 0; j < 4; j++) wmma::fill_fragment(acc[i][j], 0.0f);

    #pragma unroll
    for (int ks = 0; ks < 8; ks++) {
        wmma::fragment<wmma::matrix_a, 16, 16, 16, __half, wmma::row_major> af[2];
        wmma::load_matrix_sync(af[0], As + (wr +  0) * LDAB + ks * 16, LDAB);
        wmma::load_matrix_sync(af[1], As + (wr + 16) * LDAB + ks * 16, LDAB);
        #pragma unroll
        for (int j = 0; j < 4; j++) {
            wmma::fragment<wmma::matrix_b, 16, 16, 16, __half, wmma::row_major> bf;
            wmma::load_matrix_sync(bf, Bs + (ks * 16) * LDAB + wc + j * 16, LDAB);
            wmma::mma_sync(acc[0][j], af[0], bf, acc[0][j]);
            wmma::mma_sync(acc[1][j], af[1], bf, acc[1][j]);
        }
    }
    __syncthreads();            // done reading As/Bs; reuse as staging

    #pragma unroll
    for (int i = 0; i < 2; i++)
        #pragma unroll
        for (int j = 0; j < 4; j++)
            wmma::store_matrix_sync(Cs + (wr + i * 16) * LDC + wc + j * 16,
                                    acc[i][j], LDC, wmma::mem_row_major);
    __syncthreads();

    // --- epilogue: pack fp16 (dis already folded), store g_m coalesced ---
    {
        int r    = tid >> 1;
        int half = tid & 1;
        int m    = base + r;
        if (m < N) {
            const float* row = Cs + r * LDC + half * 64;
            uint4* dst = (uint4*)g_m + (size_t)m * 16 + half * 8;
            #pragma unroll
            for (int i = 0; i < 4; i++) {
                float4 p = *(const float4*)(row + i * 16 + 0);
                float4 q = *(const float4*)(row + i * 16 + 4);
                float4 s = *(const float4*)(row + i * 16 + 8);
                float4 t = *(const float4*)(row + i * 16 + 12);
                uint4 u0, u1;
                u0.x = pack_hf2(p.x, p.y); u0.y = pack_hf2(p.z, p.w);
                u0.z = pack_hf2(q.x, q.y); u0.w = pack_hf2(q.z, q.w);
                u1.x = pack_hf2(s.x, s.y); u1.y = pack_hf2(s.z, s.w);
                u1.z = pack_hf2(t.x, t.y); u1.w = pack_hf2(t.z, t.w);
                dst[i * 2 + 0] = u0;
                dst[i * 2 + 1] = u1;
            }
        }
    }
}

// ---------------------------------------------------------------------------
// aggregate: warp per node (R12-proven form + csr prefetch).
// y[n] = relu( dn*(sum_in m[s] + m[n]) + bias )
// ---------------------------------------------------------------------------
__device__ __forceinline__ void add_row(float4& a, int s, int lane) {
    float4 g = unpk_hf4(g_m[(size_t)s * 32 + lane]);
    a.x += g.x; a.y += g.y; a.z += g.z; a.w += g.w;
}

__global__ void __launch_bounds__(256) k_aggr(const float* __restrict__ bias, int N) {
    int w    = (int)((blockIdx.x * (unsigned)blockDim.x + threadIdx.x) >> 5);
    int lane = threadIdx.x & 31;
    if (w >= N) return;

    int beg = clampi(g_rowptr[w],     EMAX);
    int end = clampi(g_rowptr[w + 1], EMAX);
    float dn = g_dis[w];

    float4 a0 = unpk_hf4(g_m[(size_t)w * 32 + lane]);   // self term m[n]
    float4 a1 = make_float4(0.f, 0.f, 0.f, 0.f);

    int e = beg;
    for (; e < end && (e & 3); e++) add_row(a0, g_csr[e], lane);
    // 4 edges/iter, 2 accumulators; next int4 prefetched ahead of row gathers
    if (e + 4 <= end) {
        int4 s4 = *(const int4*)(g_csr + e);
        for (; e + 8 <= end; e += 4) {
            int4 n4 = *(const int4*)(g_csr + e + 4);   // prefetch next
            add_row(a0, s4.x, lane);
            add_row(a1, s4.y, lane);
            add_row(a0, s4.z, lane);
            add_row(a1, s4.w, lane);
            s4 = n4;
        }
        add_row(a0, s4.x, lane);
        add_row(a1, s4.y, lane);
        add_row(a0, s4.z, lane);
        add_row(a1, s4.w, lane);
        e += 4;
    }
    for (; e < end; e++) add_row(a1, g_csr[e], lane);

    float4 b = ((const float4*)bias)[lane];
    float y0 = fmaxf(dn * (a0.x + a1.x) + b.x, 0.0f);
    float y1 = fmaxf(dn * (a0.y + a1.y) + b.y, 0.0f);
    float y2 = fmaxf(dn * (a0.z + a1.z) + b.z, 0.0f);
    float y3 = fmaxf(dn * (a0.w + a1.w) + b.w, 0.0f);
    g_y[(size_t)w * 32 + lane] = make_uint2(pack_hf2(y0, y1), pack_hf2(y2, y3));
}

// ---------------------------------------------------------------------------
// pooling (batch sorted): y already has bias+relu
// ---------------------------------------------------------------------------
#define POOL_CHUNK 256
__global__ void __launch_bounds__(HID) k_pool(
    const int* __restrict__ batch,
    float* __restrict__ out,
    int N)
{
    int j     = threadIdx.x;
    int start = blockIdx.x * POOL_CHUNK;
    if (start >= N) return;
    int end = start + POOL_CHUNK;
    if (end > N) end = N;

    const __half* yh = (const __half*)g_y;

    int   cur = clampi(batch[start], GMAX - 1);
    float sum = 0.0f;
    float cnt = 0.0f;

    for (int r = start; r < end; r++) {
        int g = clampi(batch[r], GMAX - 1);
        if (g != cur) {
            atomicAdd(out + (size_t)cur * HID + j, sum);
            if (j == 0) atomicAdd(&g_cnt[cur], cnt);
            sum = 0.0f; cnt = 0.0f; cur = g;
        }
        sum += __half2float(yh[(size_t)r * HID + j]);
        cnt += 1.0f;
    }
    atomicAdd(out + (size_t)cur * HID + j, sum);
    if (j == 0) atomicAdd(&g_cnt[cur], cnt);
}

__global__ void k_div(float* __restrict__ out, int out_elems) {
    int i = blockIdx.x * blockDim.x + threadIdx.x;
    if (i < out_elems) out[i] /= fmaxf(g_cnt[i >> 7], 1.0f);
}

// ---------------------------------------------------------------------------
extern "C" void kernel_launch(void* const* d_in, const int* in_sizes, int n_in,
                              void* d_out, int out_size) {
    const float* x     = (const float*)d_in[0];
    const int*   ei    = (const int*)d_in[1];     // int32 (JAX x64 disabled)
    const int*   batch = (const int*)d_in[2];     // int32
    const float* Ws    = (const float*)d_in[3];
    const float* bs    = (const float*)d_in[4];
    float*       out   = (float*)d_out;

    const int N = in_sizes[0] / HID;
    const int E = in_sizes[1] / 2;
    const int* srcp = ei;
    const int* dstp = ei + E;

    const int smem = 2 * 128 * LDAB * sizeof(__half);   // 69632 B
    cudaFuncSetAttribute(k_gemm_wmma,
                         cudaFuncAttributeMaxDynamicSharedMemorySize, smem);

    const int nb_scan     = (N + SCAN_B - 1) / SCAN_B;
    const int gemm_blocks = (N + 127) / 128;
    const int aggr_blocks = (int)(((long long)N * 32 + 255) / 256);

    // launch order keeps layer-0 GEMM at index 3 (ncu capture slot)
    k_init  <<<(N + 255) / 256, 256>>>(Ws, out, N, out_size);           // 0
    k_count <<<(E + 255) / 256, 256>>>(dstp, E, N);                     // 1
    k_scan1 <<<nb_scan, SCAN_B>>>(N);                                   // 2
    k_gemm_wmma<<<gemm_blocks, 256, smem>>>(x, 0, N);                   // 3 <- profiled
    k_scan2 <<<1, SCAN_B>>>(nb_scan);                                   // 4
    k_scan3 <<<(N + 255) / 256, 256>>>(N, E);                           // 5
    k_fill  <<<(E + 255) / 256, 256>>>(srcp, dstp, E, N);               // 6

    k_aggr  <<<aggr_blocks, 256>>>(bs, N);                              // layer 0
    for (int l = 1; l < 3; l++) {
        k_gemm_wmma<<<gemm_blocks, 256, smem>>>(x, l, N);
        k_aggr  <<<aggr_blocks, 256>>>(bs + (size_t)l * HID, N);
    }

    k_pool<<<(N + POOL_CHUNK - 1) / POOL_CHUNK, HID>>>(batch, out, N);
    k_div <<<(out_size + 255) / 256, 256>>>(out, out_size);
}